// round 2
// baseline (speedup 1.0000x reference)
#include <cuda_runtime.h>
#include <cstdint>

#define FULLMASK 0xffffffffu

static __device__ __forceinline__ float ex2f_(float x){ float y; asm("ex2.approx.ftz.f32 %0, %1;" : "=f"(y) : "f"(x)); return y; }
static __device__ __forceinline__ float lg2f_(float x){ float y; asm("lg2.approx.ftz.f32 %0, %1;" : "=f"(y) : "f"(x)); return y; }

#define CRF_B 1024
#define CRF_S 1024
#define CRF_T 16
#define LOG2E_F 1.4426950408889634f
#define LN2_F   0.6931471805599453f

// per-batch NLL scratch (no allocation allowed -> device global)
__device__ float g_nll[CRF_B];

// One CRF time-step in linear domain with running log2 offset.
// K is a compile-time literal (macro), so array indexing / renorm predicate fold.
#define STEP(K) do { \
    float emj = em_c[(K)]; \
    float emL = emj * LOG2E_F; \
    float mt  = __shfl_sync(FULLMASK, emL, 0, 16) + 3.0f; \
    float f   = ex2f_(emL - mt); \
    int   tg  = __shfl_sync(FULLMASK, tag_c, (K), 16); \
    int   mk  = __shfl_sync(FULLMASK, msk_c, (K), 16); \
    float emit= __shfl_sync(FULLMASK, emj, tg, 16); \
    float tr  = s_trans[tg*16 + tgprev]; \
    float q0  = __shfl_sync(FULLMASK, p,  0, 16); \
    float q1  = __shfl_sync(FULLMASK, p,  1, 16); \
    float q2  = __shfl_sync(FULLMASK, p,  2, 16); \
    float q3  = __shfl_sync(FULLMASK, p,  3, 16); \
    float q4  = __shfl_sync(FULLMASK, p,  4, 16); \
    float q5  = __shfl_sync(FULLMASK, p,  5, 16); \
    float q6  = __shfl_sync(FULLMASK, p,  6, 16); \
    float q7  = __shfl_sync(FULLMASK, p,  7, 16); \
    float q8  = __shfl_sync(FULLMASK, p,  8, 16); \
    float q9  = __shfl_sync(FULLMASK, p,  9, 16); \
    float q10 = __shfl_sync(FULLMASK, p, 10, 16); \
    float q11 = __shfl_sync(FULLMASK, p, 11, 16); \
    float q12 = __shfl_sync(FULLMASK, p, 12, 16); \
    float q13 = __shfl_sync(FULLMASK, p, 13, 16); \
    float q14 = __shfl_sync(FULLMASK, p, 14, 16); \
    float q15 = __shfl_sync(FULLMASK, p, 15, 16); \
    float a0 = q0*Ecol[0], a1 = q1*Ecol[1], a2 = q2*Ecol[2], a3 = q3*Ecol[3]; \
    a0 = fmaf(q4,  Ecol[4],  a0); a1 = fmaf(q5,  Ecol[5],  a1); \
    a2 = fmaf(q6,  Ecol[6],  a2); a3 = fmaf(q7,  Ecol[7],  a3); \
    a0 = fmaf(q8,  Ecol[8],  a0); a1 = fmaf(q9,  Ecol[9],  a1); \
    a2 = fmaf(q10, Ecol[10], a2); a3 = fmaf(q11, Ecol[11], a3); \
    a0 = fmaf(q12, Ecol[12], a0); a1 = fmaf(q13, Ecol[13], a1); \
    a2 = fmaf(q14, Ecol[14], a2); a3 = fmaf(q15, Ecol[15], a3); \
    float acc = (a0 + a1) + (a2 + a3); \
    float pn  = acc * f; \
    p    = mk ? pn           : p; \
    off2 = mk ? (off2 + mt)  : off2; \
    gold = mk ? (gold + emit + tr) : gold; \
    lt   = mk ? tg : lt; \
    tgprev = tg; \
    if ((((K) & 7)) == 7) { \
        float r = __shfl_sync(FULLMASK, p, 0, 16); \
        float l = lg2f_(r); \
        p = p * ex2f_(-l); \
        off2 += l; \
    } \
} while (0)

__global__ void __launch_bounds__(128, 1)
crf_forward_kernel(const float* __restrict__ em,
                   const int* __restrict__ tags,
                   const int* __restrict__ mask,
                   const float* __restrict__ trans,
                   const float* __restrict__ start_t,
                   const float* __restrict__ end_t)
{
    __shared__ float s_trans[256];
    __shared__ float s_start[16];

    int tid = threadIdx.x;
    for (int i = tid; i < 256; i += 128) s_trans[i] = trans[i];
    if (tid < 16) s_start[tid] = start_t[tid];
    __syncthreads();

    const int j = tid & 15;                       // tag-state lane within group
    const int b = blockIdx.x * 8 + (tid >> 4);    // batch element (1024 total)

    const float* emp = em   + (size_t)b * CRF_S * CRF_T + j;
    const int*   tp  = tags + (size_t)b * CRF_S;
    const int*   mp  = mask + (size_t)b * CRF_S;

    // E column j in registers: Ecol[i] = exp(transitions[i][j])
    float Ecol[16];
    #pragma unroll
    for (int i = 0; i < 16; i++)
        Ecol[i] = ex2f_(__ldg(trans + i * 16 + j) * LOG2E_F);
    const float eend = ex2f_(__ldg(end_t + j) * LOG2E_F);

    // --- prefetch block 0 (t = 0..15) ---
    float em_n[16];
    #pragma unroll
    for (int u = 0; u < 16; u++) em_n[u] = __ldg(emp + u * CRF_T);
    int tag_n = __ldg(tp + j);
    int msk_n = __ldg(mp + j);

    float em_c[16];
    int   tag_c, msk_c;

    float p, off2, gold;
    int   tgprev, lt;

    // ===== block 0: init at t=0, then steps 1..15, while prefetching block 1 =====
    {
        #pragma unroll
        for (int u = 0; u < 16; u++) em_c[u] = em_n[u];
        tag_c = tag_n; msk_c = msk_n;

        // prefetch block 1
        #pragma unroll
        for (int u = 0; u < 16; u++) em_n[u] = __ldg(emp + (16 + u) * CRF_T);
        tag_n = __ldg(tp + 16 + j);
        msk_n = __ldg(mp + 16 + j);

        // t = 0 init: score0 = start + em[0]  (log2 domain, normalized to lane 0)
        float sL = (s_start[j] + em_c[0]) * LOG2E_F;
        float m0 = __shfl_sync(FULLMASK, sL, 0, 16);
        p    = ex2f_(sL - m0);
        off2 = m0;

        int   tg0   = __shfl_sync(FULLMASK, tag_c, 0, 16);
        float emit0 = __shfl_sync(FULLMASK, em_c[0], tg0, 16);
        gold   = s_start[tg0] + emit0;
        tgprev = tg0;
        lt     = tg0;

        STEP(1);  STEP(2);  STEP(3);  STEP(4);  STEP(5);
        STEP(6);  STEP(7);  STEP(8);  STEP(9);  STEP(10);
        STEP(11); STEP(12); STEP(13); STEP(14); STEP(15);
    }

    // ===== blocks 1..63 =====
    for (int nb = 1; nb < 64; nb++) {
        #pragma unroll
        for (int u = 0; u < 16; u++) em_c[u] = em_n[u];
        tag_c = tag_n; msk_c = msk_n;

        if (nb < 63) {
            const int t0 = (nb + 1) * 16;
            #pragma unroll
            for (int u = 0; u < 16; u++) em_n[u] = __ldg(emp + (t0 + u) * CRF_T);
            tag_n = __ldg(tp + t0 + j);
            msk_n = __ldg(mp + t0 + j);
        }

        STEP(0);  STEP(1);  STEP(2);  STEP(3);
        STEP(4);  STEP(5);  STEP(6);  STEP(7);
        STEP(8);  STEP(9);  STEP(10); STEP(11);
        STEP(12); STEP(13); STEP(14); STEP(15);
    }

    // ===== epilogue: logZ = (off2 + log2(sum_j p_j * exp(end_j))) * ln2 =====
    float z = p * eend;
    z += __shfl_xor_sync(FULLMASK, z, 8, 16);
    z += __shfl_xor_sync(FULLMASK, z, 4, 16);
    z += __shfl_xor_sync(FULLMASK, z, 2, 16);
    z += __shfl_xor_sync(FULLMASK, z, 1, 16);

    float logZ = (off2 + lg2f_(z)) * LN2_F;
    gold += __ldg(end_t + lt);

    if (j == 0) g_nll[b] = logZ - gold;
}

__global__ void crf_reduce_kernel(float* __restrict__ out)
{
    __shared__ float sm[256];
    int tid = threadIdx.x;
    float v = g_nll[tid] + g_nll[tid + 256] + g_nll[tid + 512] + g_nll[tid + 768];
    sm[tid] = v;
    __syncthreads();
    #pragma unroll
    for (int s = 128; s > 0; s >>= 1) {
        if (tid < s) sm[tid] += sm[tid + s];
        __syncthreads();
    }
    if (tid == 0) out[0] = sm[0] * (1.0f / 1024.0f);
}

extern "C" void kernel_launch(void* const* d_in, const int* in_sizes, int n_in,
                              void* d_out, int out_size)
{
    const float* emissions = (const float*)d_in[0];
    const int*   tags      = (const int*)d_in[1];
    const int*   mask      = (const int*)d_in[2];
    const float* trans     = (const float*)d_in[3];
    const float* start_t   = (const float*)d_in[4];
    const float* end_t     = (const float*)d_in[5];
    float* out = (float*)d_out;

    crf_forward_kernel<<<128, 128>>>(emissions, tags, mask, trans, start_t, end_t);
    crf_reduce_kernel<<<1, 256>>>(out);
}